// round 1
// baseline (speedup 1.0000x reference)
#include <cuda_runtime.h>
#include <math.h>

#define NLINKS   4096
#define PMAXF    0.1f
#define BUDGETF  100.0f
#define THREADS  256
#define VPT      16        // values per thread: 256*16 = 4096
#define NITER    22        // bisection iterations (interval 7.2/2^22 ~ 1.7e-6, Newton finishes)

__device__ __forceinline__ float clipP(float t) {
    return fminf(fmaxf(t, 0.0f), PMAXF);
}

__global__ __launch_bounds__(THREADS)
void proj_kernel(const float* __restrict__ raw, float* __restrict__ out, int nrows) {
    __shared__ float sred[2 * 8];   // double-buffered per-warp partial sums
    __shared__ float smin[8];
    __shared__ float smax[8];
    __shared__ float scnt[8];

    const int row = blockIdx.x;
    if (row >= nrows) return;

    const float* rp = raw + (size_t)row * NLINKS;
    float*       op = out + (size_t)row * NLINKS;

    const int tid  = threadIdx.x;
    const int lane = tid & 31;
    const int warp = tid >> 5;

    // ---- load row into registers (float4, coalesced), fused min/max/g(0) ----
    float v[VPT];
    const float4* rp4 = reinterpret_cast<const float4*>(rp);
    #pragma unroll
    for (int i = 0; i < VPT / 4; i++) {
        float4 q = rp4[tid + i * THREADS];
        v[4 * i + 0] = q.x;
        v[4 * i + 1] = q.y;
        v[4 * i + 2] = q.z;
        v[4 * i + 3] = q.w;
    }

    float s0 = 0.0f;
    float vmin =  1e30f;
    float vmax = -1e30f;
    #pragma unroll
    for (int i = 0; i < VPT; i++) {
        s0  += clipP(v[i]);
        vmin = fminf(vmin, v[i]);
        vmax = fmaxf(vmax, v[i]);
    }

    // warp-level combined reduction
    #pragma unroll
    for (int o = 16; o > 0; o >>= 1) {
        s0  += __shfl_xor_sync(0xffffffffu, s0, o);
        vmin = fminf(vmin, __shfl_xor_sync(0xffffffffu, vmin, o));
        vmax = fmaxf(vmax, __shfl_xor_sync(0xffffffffu, vmax, o));
    }
    if (lane == 0) {
        sred[warp] = s0;       // slot 0
        smin[warp] = vmin;
        smax[warp] = vmax;
    }
    __syncthreads();

    float g0 = 0.0f, lo = 1e30f, hi = -1e30f;
    #pragma unroll
    for (int w = 0; w < 8; w++) {
        g0 += sred[w];
        lo  = fminf(lo, smin[w]);
        hi  = fmaxf(hi, smax[w]);
    }
    lo -= PMAXF;   // g(lo) = n*PMAX >= BUDGET ; g(hi) = 0

    // ---- feasible rows: output is just clip(raw, 0, PMAX) ----
    if (g0 <= BUDGETF) {
        float4* op4 = reinterpret_cast<float4*>(op);
        #pragma unroll
        for (int i = 0; i < VPT / 4; i++) {
            float4 q;
            q.x = clipP(v[4 * i + 0]);
            q.y = clipP(v[4 * i + 1]);
            q.z = clipP(v[4 * i + 2]);
            q.w = clipP(v[4 * i + 3]);
            op4[tid + i * THREADS] = q;
        }
        return;
    }

    // ---- bisection: one __syncthreads per iteration via double-buffered smem ----
    #pragma unroll 1
    for (int it = 0; it < NITER; it++) {
        const float mid = 0.5f * (lo + hi);
        float a0 = 0.0f, a1 = 0.0f, a2 = 0.0f, a3 = 0.0f;
        #pragma unroll
        for (int i = 0; i < VPT; i += 4) {
            a0 += clipP(v[i + 0] - mid);
            a1 += clipP(v[i + 1] - mid);
            a2 += clipP(v[i + 2] - mid);
            a3 += clipP(v[i + 3] - mid);
        }
        float s = (a0 + a1) + (a2 + a3);
        #pragma unroll
        for (int o = 16; o > 0; o >>= 1)
            s += __shfl_xor_sync(0xffffffffu, s, o);

        const int slot = (it + 1) & 1;   // iter 0 uses slot 1 (slot 0 held init data)
        if (lane == 0) sred[slot * 8 + warp] = s;
        __syncthreads();

        float g = 0.0f;
        #pragma unroll
        for (int w = 0; w < 8; w++) g += sred[slot * 8 + w];

        if (g > BUDGETF) lo = mid; else hi = mid;
    }

    const float tau0 = 0.5f * (lo + hi);

    // ---- Newton / implicit-function correction: exact within the linear piece ----
    float gs = 0.0f, cnt = 0.0f;
    #pragma unroll
    for (int i = 0; i < VPT; i++) {
        const float t = v[i] - tau0;
        gs += clipP(t);
        cnt += (t > 0.0f && t < PMAXF) ? 1.0f : 0.0f;
    }
    #pragma unroll
    for (int o = 16; o > 0; o >>= 1) {
        gs  += __shfl_xor_sync(0xffffffffu, gs, o);
        cnt += __shfl_xor_sync(0xffffffffu, cnt, o);
    }
    // last bisection iter wrote slot ((NITER-1+1)&1) = NITER&1 = 0 -> use slot 1 here
    if (lane == 0) {
        sred[8 + warp] = gs;
        scnt[warp]     = cnt;
    }
    __syncthreads();
    float gsum = 0.0f, csum = 0.0f;
    #pragma unroll
    for (int w = 0; w < 8; w++) {
        gsum += sred[8 + w];
        csum += scnt[w];
    }
    const float tau = tau0 + (gsum - BUDGETF) / fmaxf(csum, 1.0f);

    // ---- write projected row ----
    float4* op4 = reinterpret_cast<float4*>(op);
    #pragma unroll
    for (int i = 0; i < VPT / 4; i++) {
        float4 q;
        q.x = clipP(v[4 * i + 0] - tau);
        q.y = clipP(v[4 * i + 1] - tau);
        q.z = clipP(v[4 * i + 2] - tau);
        q.w = clipP(v[4 * i + 3] - tau);
        op4[tid + i * THREADS] = q;
    }
}

extern "C" void kernel_launch(void* const* d_in, const int* in_sizes, int n_in,
                              void* d_out, int out_size) {
    const float* raw = (const float*)d_in[0];
    float*       out = (float*)d_out;
    const int nrows = in_sizes[0] / NLINKS;
    proj_kernel<<<nrows, THREADS>>>(raw, out, nrows);
}

// round 3
// speedup vs baseline: 1.5948x; 1.5948x over previous
#include <cuda_runtime.h>
#include <math.h>

#define NLINKS   4096
#define PMAXF    0.1f
#define BUDGETF  100.0f
#define THREADS  256
#define VPT      16        // 256*16 = 4096
#define PLO      0.5f      // probe bracket low
#define PHI      0.9f      // probe bracket high
#define HB       1.0f      // saturation boundary (>= HB -> always PMAX for tau<=PHI)
#define CAP1     1024      // stage-1 active capacity (4KB smem)
#define SLOTS1   4         // CAP1/THREADS
#define CAP2     256       // stage-2 active capacity (warp0 registers)
#define SLOTS2   8         // CAP2/32
#define NA       6         // block bisection iters (0.4 -> 6.25e-3)
#define NB       12        // warp0 bisection iters (-> 1.5e-6)
#define NFALL    26        // fallback bisection iters

__device__ __forceinline__ float clipP(float t) {
    return fminf(fmaxf(t, 0.0f), PMAXF);
}

__global__ __launch_bounds__(THREADS)
void proj_kernel(const float* __restrict__ raw, float* __restrict__ out, int nrows) {
    __shared__ float sAct[CAP1];
    __shared__ float sP[16];     // partials, two banks of 8
    __shared__ float sQ[16];
    __shared__ float sTau;
    __shared__ int   sCnt;
    __shared__ int   sCnt2;

    const int row = blockIdx.x;
    if (row >= nrows) return;

    const float* rp = raw + (size_t)row * NLINKS;
    float*       op = out + (size_t)row * NLINKS;

    const int tid  = threadIdx.x;
    const int lane = tid & 31;
    const int warp = tid >> 5;

    if (tid == 0) { sCnt = 0; sCnt2 = 0; }

    // ---- load row into registers ----
    float v[VPT];
    const float4* rp4 = reinterpret_cast<const float4*>(rp);
    #pragma unroll
    for (int i = 0; i < VPT / 4; i++) {
        float4 q = rp4[tid + i * THREADS];
        v[4*i+0] = q.x; v[4*i+1] = q.y; v[4*i+2] = q.z; v[4*i+3] = q.w;
    }

    // ---- init pass: g(0), active-band count, high count ----
    float s0 = 0.0f, cHigh = 0.0f;
    int nact = 0;
    #pragma unroll
    for (int i = 0; i < VPT; i++) {
        const float x = v[i];
        s0 += clipP(x);
        const bool a = (x > PLO) && (x < HB);
        nact += a ? 1 : 0;
        cHigh += (x >= HB) ? 1.0f : 0.0f;
    }
    #pragma unroll
    for (int o = 16; o > 0; o >>= 1) {
        s0    += __shfl_xor_sync(0xffffffffu, s0, o);
        cHigh += __shfl_xor_sync(0xffffffffu, cHigh, o);
    }
    if (lane == 0) { sP[warp] = s0; sQ[warp] = cHigh; }
    __syncthreads();

    float g0 = 0.0f, Ch = 0.0f;
    #pragma unroll
    for (int w = 0; w < 8; w++) { g0 += sP[w]; Ch += sQ[w]; }

    // ---- feasible rows: just clip ----
    if (g0 <= BUDGETF) {
        float4* op4 = reinterpret_cast<float4*>(op);
        #pragma unroll
        for (int i = 0; i < VPT / 4; i++) {
            float4 q;
            q.x = clipP(v[4*i+0]); q.y = clipP(v[4*i+1]);
            q.z = clipP(v[4*i+2]); q.w = clipP(v[4*i+3]);
            op4[tid + i * THREADS] = q;
        }
        return;
    }

    // ---- stage-1 compaction of band (PLO, HB) into smem ----
    {
        int inc = nact;
        #pragma unroll
        for (int o = 1; o < 32; o <<= 1) {
            int t = __shfl_up_sync(0xffffffffu, inc, o);
            if (lane >= o) inc += t;
        }
        const int excl = inc - nact;
        const int wtot = __shfl_sync(0xffffffffu, inc, 31);
        int wbase = 0;
        if (lane == 0) wbase = atomicAdd(&sCnt, wtot);
        wbase = __shfl_sync(0xffffffffu, wbase, 0);
        int idx = wbase + excl;
        #pragma unroll
        for (int i = 0; i < VPT; i++) {
            const float x = v[i];
            if ((x > PLO) && (x < HB)) {
                if (idx < CAP1) sAct[idx] = x;
                idx++;
            }
        }
    }
    __syncthreads();
    const int nAct = sCnt;

    float tau = 0.0f;
    bool done = false;

    if (nAct <= CAP1) {
        // sentinel-pad so every thread evaluates exactly SLOTS1 values
        for (int i = nAct + tid; i < CAP1; i += THREADS) sAct[i] = -1.0e30f;
        __syncthreads();

        float a[SLOTS1];
        #pragma unroll
        for (int j = 0; j < SLOTS1; j++) a[j] = sAct[tid + j * THREADS];
        const float C = Ch * PMAXF;

        // verify bracket g(PLO) >= B >= g(PHI) using compacted identity
        float sL = 0.0f, sH = 0.0f;
        #pragma unroll
        for (int j = 0; j < SLOTS1; j++) {
            sL += clipP(a[j] - PLO);
            sH += clipP(a[j] - PHI);
        }
        #pragma unroll
        for (int o = 16; o > 0; o >>= 1) {
            sL += __shfl_xor_sync(0xffffffffu, sL, o);
            sH += __shfl_xor_sync(0xffffffffu, sH, o);
        }
        if (lane == 0) { sP[8 + warp] = sL; sQ[8 + warp] = sH; }
        __syncthreads();
        float gL = C, gH = C;
        #pragma unroll
        for (int w = 0; w < 8; w++) { gL += sP[8 + w]; gH += sQ[8 + w]; }

        if (gL >= BUDGETF && gH <= BUDGETF) {
            float lo = PLO, hi = PHI;

            // ---- stage A: block bisection on 4-slot active set ----
            #pragma unroll 1
            for (int it = 0; it < NA; it++) {
                const float mid = 0.5f * (lo + hi);
                float s = 0.0f;
                #pragma unroll
                for (int j = 0; j < SLOTS1; j++) s += clipP(a[j] - mid);
                #pragma unroll
                for (int o = 16; o > 0; o >>= 1) s += __shfl_xor_sync(0xffffffffu, s, o);
                const int slot = it & 1;
                if (lane == 0) sP[slot * 8 + warp] = s;
                __syncthreads();
                float g = C;
                #pragma unroll
                for (int w = 0; w < 8; w++) g += sP[slot * 8 + w];
                if (g > BUDGETF) lo = mid; else hi = mid;
            }

            // ---- recompact to stage-2 set (band (lo, hi+PMAX)) ----
            int nact2 = 0;
            float cHigh2 = 0.0f;
            #pragma unroll
            for (int j = 0; j < SLOTS1; j++) {
                const float x = a[j];
                const bool act2 = (x > lo) && ((x - hi) < PMAXF);
                nact2 += act2 ? 1 : 0;
                cHigh2 += ((x - hi) >= PMAXF) ? 1.0f : 0.0f;
            }
            int inc = nact2;
            #pragma unroll
            for (int o = 1; o < 32; o <<= 1) {
                int t = __shfl_up_sync(0xffffffffu, inc, o);
                if (lane >= o) inc += t;
            }
            const int excl = inc - nact2;
            const int wtot = __shfl_sync(0xffffffffu, inc, 31);
            float cw = cHigh2;
            #pragma unroll
            for (int o = 16; o > 0; o >>= 1) cw += __shfl_xor_sync(0xffffffffu, cw, o);
            int wbase = 0;
            if (lane == 0) wbase = atomicAdd(&sCnt2, wtot);
            wbase = __shfl_sync(0xffffffffu, wbase, 0);
            int idx = wbase + excl;
            #pragma unroll
            for (int j = 0; j < SLOTS1; j++) {
                const float x = a[j];
                if ((x > lo) && ((x - hi) < PMAXF)) {
                    if (idx < CAP2) sAct[idx] = x;
                    idx++;
                }
            }
            if (lane == 0) sQ[warp] = cw;
            __syncthreads();
            const int nAct2 = sCnt2;
            float C2 = C;
            #pragma unroll
            for (int w = 0; w < 8; w++) C2 += sQ[w] * PMAXF;

            if (nAct2 <= CAP2) {
                for (int i = nAct2 + tid; i < CAP2; i += THREADS) sAct[i] = -1.0e30f;
                __syncthreads();

                // ---- stage B: warp 0 alone, registers + shuffles, no barriers ----
                if (warp == 0) {
                    float b[SLOTS2];
                    #pragma unroll
                    for (int k = 0; k < SLOTS2; k++) b[k] = sAct[lane + k * 32];

                    float blo = lo, bhi = hi;
                    #pragma unroll 1
                    for (int it = 0; it < NB; it++) {
                        const float mid = 0.5f * (blo + bhi);
                        float s = 0.0f;
                        #pragma unroll
                        for (int k = 0; k < SLOTS2; k++) s += clipP(b[k] - mid);
                        #pragma unroll
                        for (int o = 16; o > 0; o >>= 1) s += __shfl_xor_sync(0xffffffffu, s, o);
                        if (C2 + s > BUDGETF) blo = mid; else bhi = mid;
                    }
                    const float tau0 = 0.5f * (blo + bhi);

                    // Newton / implicit-function correction (exact in linear piece)
                    float gs = 0.0f, cnt = 0.0f;
                    #pragma unroll
                    for (int k = 0; k < SLOTS2; k++) {
                        const float t = b[k] - tau0;
                        gs += clipP(t);
                        cnt += (t > 0.0f && t < PMAXF) ? 1.0f : 0.0f;
                    }
                    #pragma unroll
                    for (int o = 16; o > 0; o >>= 1) {
                        gs  += __shfl_xor_sync(0xffffffffu, gs, o);
                        cnt += __shfl_xor_sync(0xffffffffu, cnt, o);
                    }
                    if (lane == 0)
                        sTau = tau0 + (C2 + gs - BUDGETF) / fmaxf(cnt, 1.0f);
                }
                __syncthreads();
                tau = sTau;
                done = true;
            }
        }
    }

    // ---- fallback: full-row bisection (rare / adversarial inputs) ----
    if (!done) {
        float vmin = 1e30f, vmax = -1e30f;
        #pragma unroll
        for (int i = 0; i < VPT; i++) {
            vmin = fminf(vmin, v[i]);
            vmax = fmaxf(vmax, v[i]);
        }
        #pragma unroll
        for (int o = 16; o > 0; o >>= 1) {
            vmin = fminf(vmin, __shfl_xor_sync(0xffffffffu, vmin, o));
            vmax = fmaxf(vmax, __shfl_xor_sync(0xffffffffu, vmax, o));
        }
        if (lane == 0) { sP[warp] = vmin; sQ[warp] = vmax; }
        __syncthreads();
        float lo = 1e30f, hi = -1e30f;
        #pragma unroll
        for (int w = 0; w < 8; w++) {
            lo = fminf(lo, sP[w]);
            hi = fmaxf(hi, sQ[w]);
        }
        lo -= PMAXF;

        #pragma unroll 1
        for (int it = 0; it < NFALL; it++) {
            const float mid = 0.5f * (lo + hi);
            float s = 0.0f;
            #pragma unroll
            for (int i = 0; i < VPT; i++) s += clipP(v[i] - mid);
            #pragma unroll
            for (int o = 16; o > 0; o >>= 1) s += __shfl_xor_sync(0xffffffffu, s, o);
            const int slot = (it + 1) & 1;   // iter 0 -> bank 1 (bank 0 just read)
            if (lane == 0) sP[slot * 8 + warp] = s;
            __syncthreads();
            float g = 0.0f;
            #pragma unroll
            for (int w = 0; w < 8; w++) g += sP[slot * 8 + w];
            if (g > BUDGETF) lo = mid; else hi = mid;
        }
        const float tau0 = 0.5f * (lo + hi);

        float gs = 0.0f, cnt = 0.0f;
        #pragma unroll
        for (int i = 0; i < VPT; i++) {
            const float t = v[i] - tau0;
            gs += clipP(t);
            cnt += (t > 0.0f && t < PMAXF) ? 1.0f : 0.0f;
        }
        #pragma unroll
        for (int o = 16; o > 0; o >>= 1) {
            gs  += __shfl_xor_sync(0xffffffffu, gs, o);
            cnt += __shfl_xor_sync(0xffffffffu, cnt, o);
        }
        // last fallback iter wrote bank (NFALL)&1 = 0 -> use bank 1 here
        if (lane == 0) { sP[8 + warp] = gs; sQ[8 + warp] = cnt; }
        __syncthreads();
        float gsum = 0.0f, csum = 0.0f;
        #pragma unroll
        for (int w = 0; w < 8; w++) { gsum += sP[8 + w]; csum += sQ[8 + w]; }
        tau = tau0 + (gsum - BUDGETF) / fmaxf(csum, 1.0f);
    }

    // ---- final projected write ----
    float4* op4 = reinterpret_cast<float4*>(op);
    #pragma unroll
    for (int i = 0; i < VPT / 4; i++) {
        float4 q;
        q.x = clipP(v[4*i+0] - tau);
        q.y = clipP(v[4*i+1] - tau);
        q.z = clipP(v[4*i+2] - tau);
        q.w = clipP(v[4*i+3] - tau);
        op4[tid + i * THREADS] = q;
    }
}

extern "C" void kernel_launch(void* const* d_in, const int* in_sizes, int n_in,
                              void* d_out, int out_size) {
    const float* raw = (const float*)d_in[0];
    float*       out = (float*)d_out;
    const int nrows = in_sizes[0] / NLINKS;
    proj_kernel<<<nrows, THREADS>>>(raw, out, nrows);
}